// round 13
// baseline (speedup 1.0000x reference)
#include <cuda_runtime.h>
#include <cuda.h>
#include <cuda_fp16.h>
#include <cstdint>

// ---------------------------------------------------------------------------
// Problem dims
// ---------------------------------------------------------------------------
#define NROWS 8192
#define DIN   4096
#define DOUT  4096

// GEMM tiling
#define BM 128
#define BN 256
#define BK 64                       // 64 fp16 = 128B rows (SW128)
#define STAGES 4
#define NCHUNK (DIN / BK)           // 64

#define A_BYTES (BM * BK * 2)       // 16384
#define B_BYTES (BN * BK * 2)       // 32768
#define STAGE_BYTES (A_BYTES + B_BYTES)   // 49152

// SMEM offsets (from 1024-aligned base): [0..31] full mbars, [32..63] empty mbars
#define OFF_FULL  0
#define OFF_EMPTY 32
#define OFF_DATA  1024
#define SMEM_NEED (OFF_DATA + STAGES * STAGE_BYTES + 1024)   // align slack

#define NTHREADS 288                // 8 compute warps + 1 producer warp

// fp16 scratch (allocation-free: __device__ globals)
__device__ __align__(1024) __half g_xh[(size_t)NROWS * DIN];   // 64 MiB
__device__ __align__(1024) __half g_wh[(size_t)DOUT * DIN];    // 32 MiB

// ---------------------------------------------------------------------------
// PTX helpers (baseline sm_90 features only — NO 'a'-suffix instructions)
// ---------------------------------------------------------------------------
__device__ __forceinline__ uint32_t elect_one_pred() {
    uint32_t pred;
    asm volatile(
        "{\n\t.reg .pred p;\n\telect.sync _|p, 0xFFFFFFFF;\n\t"
        "selp.b32 %0, 1, 0, p;\n\t}" : "=r"(pred));
    return pred;
}

__device__ __forceinline__ uint32_t smem_to_u32(const void* p) {
    uint32_t a;
    asm("{ .reg .u64 t; cvta.to.shared.u64 t, %1; cvt.u32.u64 %0, t; }"
        : "=r"(a) : "l"(p));
    return a;
}

#define MBARRIER_INIT(mbar, count) \
    asm volatile("mbarrier.init.shared.b64 [%0], %1;" \
        :: "r"((uint32_t)(mbar)), "r"((uint32_t)(count)) : "memory")

#define MBARRIER_EXPECT_TX(mbar, tx_bytes) \
    asm volatile("mbarrier.arrive.expect_tx.shared.b64 _, [%0], %1;" \
        :: "r"((uint32_t)(mbar)), "r"((uint32_t)(tx_bytes)) : "memory")

#define MBARRIER_ARRIVE(mbar) \
    asm volatile("mbarrier.arrive.shared.b64 _, [%0];" \
        :: "r"((uint32_t)(mbar)) : "memory")

#define MBARRIER_WAIT_PARITY(mbar, phase_parity) do { \
    uint32_t _mbar = (uint32_t)(mbar); \
    uint32_t _parity = (uint32_t)(phase_parity); \
    uint32_t _done_; \
    asm volatile( \
        "{\n\t.reg .pred p;\n\t" \
        "mbarrier.try_wait.parity.acquire.cta.shared::cta.b64 p, [%1], %2;\n\t" \
        "selp.b32 %0, 1, 0, p;\n\t}" \
        : "=r"(_done_) : "r"(_mbar), "r"(_parity) : "memory"); \
    if (!_done_) { \
        asm volatile( \
            "{\n\t.reg .pred P1;\n\t" \
            "WAIT_LOOP_%=:\n\t" \
            "mbarrier.try_wait.parity.acquire.cta.shared::cta.b64 P1, [%0], %1, 0x989680;\n\t" \
            "@P1 bra.uni WAIT_DONE_%=;\n\t" \
            "bra.uni WAIT_LOOP_%=;\n\t" \
            "WAIT_DONE_%=:\n\t}" \
            :: "r"(_mbar), "r"(_parity) : "memory"); \
    } \
} while (0)

#define TMA_LOAD_3D(smem_addr, tensor_map, cx, cy, cz, mbar) \
    asm volatile( \
        "cp.async.bulk.tensor.3d.shared::cta.global.tile.mbarrier::complete_tx::bytes " \
        "[%0], [%1, {%2, %3, %4}], [%5];" \
        :: "r"((uint32_t)(smem_addr)), "l"(tensor_map), \
           "r"((int32_t)(cx)), "r"((int32_t)(cy)), "r"((int32_t)(cz)), \
           "r"((uint32_t)(mbar)) : "memory")

#define FENCE_PROXY_ASYNC_SHARED_CTA() \
    asm volatile("fence.proxy.async.shared::cta;" ::: "memory")

// ldmatrix x4 (non-transposed), SW128-swizzled shared addresses
__device__ __forceinline__ void ldsm_x4(uint32_t& r0, uint32_t& r1,
                                        uint32_t& r2, uint32_t& r3, uint32_t addr) {
    asm volatile("ldmatrix.sync.aligned.m8n8.x4.shared.b16 {%0,%1,%2,%3}, [%4];"
                 : "=r"(r0), "=r"(r1), "=r"(r2), "=r"(r3) : "r"(addr));
}

// fp16 HMMA, fp32 accumulate
__device__ __forceinline__ void mma16816(float* c, const uint32_t* a, const uint32_t* b) {
    asm volatile(
        "mma.sync.aligned.m16n8k16.row.col.f32.f16.f16.f32 "
        "{%0,%1,%2,%3}, {%4,%5,%6,%7}, {%8,%9}, {%0,%1,%2,%3};"
        : "+f"(c[0]), "+f"(c[1]), "+f"(c[2]), "+f"(c[3])
        : "r"(a[0]), "r"(a[1]), "r"(a[2]), "r"(a[3]), "r"(b[0]), "r"(b[1]));
}

// ---------------------------------------------------------------------------
// Conversion kernels: fp32 -> fp16 (x), fp32 -> sign() fp16 (weight)
// ---------------------------------------------------------------------------
__device__ __forceinline__ uint32_t pack2h(float a, float b) {
    __half2 h = __floats2half2_rn(a, b);
    return *reinterpret_cast<uint32_t*>(&h);
}
__device__ __forceinline__ float fsgn(float v) {
    return (v > 0.0f) ? 1.0f : ((v < 0.0f) ? -1.0f : 0.0f);
}

__global__ void cvt_x_kernel(const float4* __restrict__ in, uint4* __restrict__ outv, int n8) {
    int i = blockIdx.x * blockDim.x + threadIdx.x;
    if (i < n8) {
        float4 a = in[2 * i];
        float4 b = in[2 * i + 1];
        uint4 o;
        o.x = pack2h(a.x, a.y); o.y = pack2h(a.z, a.w);
        o.z = pack2h(b.x, b.y); o.w = pack2h(b.z, b.w);
        outv[i] = o;
    }
}

__global__ void cvt_w_kernel(const float4* __restrict__ in, uint4* __restrict__ outv, int n8) {
    int i = blockIdx.x * blockDim.x + threadIdx.x;
    if (i < n8) {
        float4 a = in[2 * i];
        float4 b = in[2 * i + 1];
        uint4 o;
        o.x = pack2h(fsgn(a.x), fsgn(a.y)); o.y = pack2h(fsgn(a.z), fsgn(a.w));
        o.z = pack2h(fsgn(b.x), fsgn(b.y)); o.w = pack2h(fsgn(b.z), fsgn(b.w));
        outv[i] = o;
    }
}

// ---------------------------------------------------------------------------
// GEMM: TMA pipeline (4 stages) + ldmatrix + mma.sync m16n8k16
//   8 compute warps: 2 (M) x 4 (N), warp tile 64x64, + 1 producer warp
// ---------------------------------------------------------------------------
__global__ void __launch_bounds__(NTHREADS, 1)
mmf_gemm_kernel(const __grid_constant__ CUtensorMap tmap_a,
                const __grid_constant__ CUtensorMap tmap_b,
                const float* __restrict__ bias,
                const float* __restrict__ scale,
                float* __restrict__ out) {
    extern __shared__ char smem_raw[];
    uint32_t sb0 = smem_to_u32(smem_raw);
    uint32_t sb  = (sb0 + 1023u) & ~1023u;   // 1024-aligned (SW128)

    const int tid  = threadIdx.x;
    const int wid  = tid >> 5;
    const int lane = tid & 31;

    // Supertiles of 8 m-tiles x 16 n-tiles for L2 locality
    const int cid   = blockIdx.x;
    const int grp   = cid >> 7;            // 128 CTAs per supertile group
    const int w     = cid & 127;
    const int m0    = ((grp << 3) + (w & 7)) * BM;
    const int n0    = (w >> 3) * BN;

    if (tid == 0) {
        #pragma unroll
        for (int s = 0; s < STAGES; s++) {
            MBARRIER_INIT(sb + OFF_FULL  + 8 * s, 1);   // tx-driven
            MBARRIER_INIT(sb + OFF_EMPTY + 8 * s, 8);   // 8 compute warps
        }
        FENCE_PROXY_ASYNC_SHARED_CTA();
    }
    __syncthreads();

    // ---------------- producer warp (wid == 8) ----------------
    if (wid == 8) {
        if (elect_one_pred()) {
            for (int c = 0; c < NCHUNK; c++) {
                const int s = c & (STAGES - 1);
                if (c >= STAGES)
                    MBARRIER_WAIT_PARITY(sb + OFF_EMPTY + 8 * s,
                                         (uint32_t)(((c - STAGES) >> 2) & 1));
                const uint32_t fb = sb + OFF_FULL + 8 * s;
                MBARRIER_EXPECT_TX(fb, STAGE_BYTES);
                const uint32_t abase = sb + OFF_DATA + s * STAGE_BYTES;
                TMA_LOAD_3D(abase,           &tmap_a, c * BK, m0, 0, fb);
                TMA_LOAD_3D(abase + A_BYTES, &tmap_b, c * BK, n0, 0, fb);
            }
        }
        return;
    }

    // ---------------- compute warps (wid 0..7) ----------------
    const int wm = wid & 1;        // 0..1  -> rows [wm*64, +64)
    const int wn = wid >> 1;       // 0..3  -> cols [wn*64, +64)

    // ldmatrix lane addressing (SW128-swizzled)
    // A: 16x16 tiles, lanes 0..15 rows klo, 16..31 rows khi
    const int rA    = lane & 15;                 // row within 16-tile
    const int kbA   = (lane >> 4) * 16;          // 16B column offset
    const int mskA  = (rA & 7) << 4;
    // B: two n8-tiles per x4: q=l>>3: {nlo/klo, nlo/khi, nhi/klo, nhi/khi}
    const int q     = lane >> 3;
    const int rB    = ((q >> 1) << 3) + (lane & 7);
    const int kbB   = (q & 1) * 16;
    const int mskB  = (lane & 7) << 4;

    float acc[4][8][4];
    #pragma unroll
    for (int i = 0; i < 4; i++)
        #pragma unroll
        for (int j = 0; j < 8; j++)
            #pragma unroll
            for (int t = 0; t < 4; t++) acc[i][j][t] = 0.0f;

    for (int c = 0; c < NCHUNK; c++) {
        const int s = c & (STAGES - 1);
        MBARRIER_WAIT_PARITY(sb + OFF_FULL + 8 * s, (uint32_t)((c >> 2) & 1));
        const uint32_t aT = sb + OFF_DATA + s * STAGE_BYTES;
        const uint32_t bT = aT + A_BYTES;

        #pragma unroll
        for (int ks = 0; ks < 4; ks++) {
            uint32_t af[4][4];
            uint32_t bf[4][4];
            const int kA = (ks * 32 + kbA) ^ mskA;
            const int kB = (ks * 32 + kbB) ^ mskB;
            #pragma unroll
            for (int i = 0; i < 4; i++) {
                const int row = wm * 64 + i * 16 + rA;
                ldsm_x4(af[i][0], af[i][1], af[i][2], af[i][3],
                        aT + row * 128 + kA);
            }
            #pragma unroll
            for (int j2 = 0; j2 < 4; j2++) {
                const int row = wn * 64 + j2 * 16 + rB;
                ldsm_x4(bf[j2][0], bf[j2][1], bf[j2][2], bf[j2][3],
                        bT + row * 128 + kB);
            }
            #pragma unroll
            for (int i = 0; i < 4; i++) {
                #pragma unroll
                for (int j2 = 0; j2 < 4; j2++) {
                    mma16816(acc[i][2 * j2 + 0], af[i], &bf[j2][0]);
                    mma16816(acc[i][2 * j2 + 1], af[i], &bf[j2][2]);
                }
            }
        }
        // all this warp's reads of stage s are complete (mma issued in-order)
        if ((lane & 31) == 0) MBARRIER_ARRIVE(sb + OFF_EMPTY + 8 * s);
    }

    // ---------------- epilogue: out = scale * (acc + bias) ----------------
    const float scl = __ldg(scale);
    const int gid = lane >> 2;     // 0..7
    const int tig = lane & 3;      // 0..3

    float2 bb[8];
    #pragma unroll
    for (int j = 0; j < 8; j++) {
        const int col = n0 + wn * 64 + j * 8 + tig * 2;
        bb[j] = *reinterpret_cast<const float2*>(bias + col);
    }

    #pragma unroll
    for (int i = 0; i < 4; i++) {
        const int row0 = m0 + wm * 64 + i * 16 + gid;
        float* p0 = out + (size_t)row0 * DOUT;
        float* p1 = p0 + (size_t)8 * DOUT;
        #pragma unroll
        for (int j = 0; j < 8; j++) {
            const int col = n0 + wn * 64 + j * 8 + tig * 2;
            float2 v0, v1;
            v0.x = scl * (acc[i][j][0] + bb[j].x);
            v0.y = scl * (acc[i][j][1] + bb[j].y);
            v1.x = scl * (acc[i][j][2] + bb[j].x);
            v1.y = scl * (acc[i][j][3] + bb[j].y);
            *reinterpret_cast<float2*>(p0 + col) = v0;
            *reinterpret_cast<float2*>(p1 + col) = v1;
        }
    }
}

// ---------------------------------------------------------------------------
// Host launch
// ---------------------------------------------------------------------------
typedef CUresult (*PFN_encodeTiled_t)(
    CUtensorMap*, CUtensorMapDataType, cuuint32_t, void*,
    const cuuint64_t*, const cuuint64_t*, const cuuint32_t*, const cuuint32_t*,
    CUtensorMapInterleave, CUtensorMapSwizzle, CUtensorMapL2promotion,
    CUtensorMapFloatOOBfill);

extern "C" void kernel_launch(void* const* d_in, const int* in_sizes, int n_in,
                              void* d_out, int out_size) {
    (void)in_sizes; (void)n_in; (void)out_size;
    const float* x     = (const float*)d_in[0];
    const float* wgt   = (const float*)d_in[1];
    const float* bias  = (const float*)d_in[2];
    const float* scale = (const float*)d_in[3];
    float* out = (float*)d_out;

    void *xh = nullptr, *wh = nullptr;
    cudaGetSymbolAddress(&xh, g_xh);
    cudaGetSymbolAddress(&wh, g_wh);

    // 1) fp32 -> fp16 conversions into scratch
    {
        const int n8x = (NROWS * DIN) / 8;
        const int n8w = (DOUT * DIN) / 8;
        cvt_x_kernel<<<(n8x + 255) / 256, 256>>>((const float4*)x, (uint4*)xh, n8x);
        cvt_w_kernel<<<(n8w + 255) / 256, 256>>>((const float4*)wgt, (uint4*)wh, n8w);
    }

    // 2) TMA descriptors
    PFN_encodeTiled_t encode = nullptr;
    {
        void* pfn = nullptr;
        cudaDriverEntryPointQueryResult qr;
#if CUDART_VERSION >= 12050
        cudaGetDriverEntryPointByVersion("cuTensorMapEncodeTiled", &pfn, 12000,
                                         cudaEnableDefault, &qr);
#else
        cudaGetDriverEntryPoint("cuTensorMapEncodeTiled", &pfn,
                                cudaEnableDefault, &qr);
#endif
        encode = (PFN_encodeTiled_t)pfn;
    }

    CUtensorMap ta{}, tb{};
    {
        cuuint64_t dimsA[3] = {DIN, NROWS, 1};
        cuuint64_t strA[2]  = {(cuuint64_t)DIN * 2, (cuuint64_t)NROWS * DIN * 2};
        cuuint32_t boxA[3]  = {BK, BM, 1};      // 64 fp16 = 128B rows (SW128)
        cuuint32_t es[3]    = {1, 1, 1};
        encode(&ta, CU_TENSOR_MAP_DATA_TYPE_FLOAT16, 3, xh, dimsA, strA, boxA, es,
               CU_TENSOR_MAP_INTERLEAVE_NONE, CU_TENSOR_MAP_SWIZZLE_128B,
               CU_TENSOR_MAP_L2_PROMOTION_L2_128B, CU_TENSOR_MAP_FLOAT_OOB_FILL_NONE);

        cuuint64_t dimsB[3] = {DIN, DOUT, 1};
        cuuint64_t strB[2]  = {(cuuint64_t)DIN * 2, (cuuint64_t)DOUT * DIN * 2};
        cuuint32_t boxB[3]  = {BK, BN, 1};      // 256-row B tile
        encode(&tb, CU_TENSOR_MAP_DATA_TYPE_FLOAT16, 3, wh, dimsB, strB, boxB, es,
               CU_TENSOR_MAP_INTERLEAVE_NONE, CU_TENSOR_MAP_SWIZZLE_128B,
               CU_TENSOR_MAP_L2_PROMOTION_L2_128B, CU_TENSOR_MAP_FLOAT_OOB_FILL_NONE);
    }

    // 3) GEMM: 1024 CTAs x 288 threads, ~194KB dyn SMEM, 1 CTA/SM
    cudaFuncSetAttribute(mmf_gemm_kernel,
                         cudaFuncAttributeMaxDynamicSharedMemorySize, SMEM_NEED);
    mmf_gemm_kernel<<<(NROWS / BM) * (DOUT / BN), NTHREADS, SMEM_NEED>>>(
        ta, tb, bias, scale, out);
}

// round 14
// speedup vs baseline: 1.0018x; 1.0018x over previous
#include <cuda_runtime.h>
#include <cuda.h>
#include <cuda_fp16.h>
#include <cstdint>

// ---------------------------------------------------------------------------
// Problem dims
// ---------------------------------------------------------------------------
#define NROWS 8192
#define DIN   4096
#define DOUT  4096

// GEMM tiling
#define BM 128
#define BN 256
#define BK 64                       // 64 fp16 = 128B rows (SW128)
#define STAGES 4
#define NCHUNK (DIN / BK)           // 64

#define A_BYTES (BM * BK * 2)       // 16384
#define B_BYTES (BN * BK * 2)       // 32768
#define STAGE_BYTES (A_BYTES + B_BYTES)   // 49152

// SMEM offsets (from 1024-aligned base): [0..31] full mbars, [32..63] empty mbars
#define OFF_FULL  0
#define OFF_EMPTY 32
#define OFF_DATA  1024
#define SMEM_NEED (OFF_DATA + STAGES * STAGE_BYTES + 1024)   // align slack

#define NTHREADS 288                // 8 compute warps + 1 producer warp

// fp16 scratch (allocation-free: __device__ globals)
__device__ __align__(1024) __half g_xh[(size_t)NROWS * DIN];   // 64 MiB
__device__ __align__(1024) __half g_wh[(size_t)DOUT * DIN];    // 32 MiB

// ---------------------------------------------------------------------------
// PTX helpers (baseline sm_90 features only — NO 'a'-suffix instructions)
// ---------------------------------------------------------------------------
__device__ __forceinline__ uint32_t elect_one_pred() {
    uint32_t pred;
    asm volatile(
        "{\n\t.reg .pred p;\n\telect.sync _|p, 0xFFFFFFFF;\n\t"
        "selp.b32 %0, 1, 0, p;\n\t}" : "=r"(pred));
    return pred;
}

__device__ __forceinline__ uint32_t smem_to_u32(const void* p) {
    uint32_t a;
    asm("{ .reg .u64 t; cvta.to.shared.u64 t, %1; cvt.u32.u64 %0, t; }"
        : "=r"(a) : "l"(p));
    return a;
}

#define MBARRIER_INIT(mbar, count) \
    asm volatile("mbarrier.init.shared.b64 [%0], %1;" \
        :: "r"((uint32_t)(mbar)), "r"((uint32_t)(count)) : "memory")

#define MBARRIER_EXPECT_TX(mbar, tx_bytes) \
    asm volatile("mbarrier.arrive.expect_tx.shared.b64 _, [%0], %1;" \
        :: "r"((uint32_t)(mbar)), "r"((uint32_t)(tx_bytes)) : "memory")

#define MBARRIER_ARRIVE(mbar) \
    asm volatile("mbarrier.arrive.shared.b64 _, [%0];" \
        :: "r"((uint32_t)(mbar)) : "memory")

#define MBARRIER_WAIT_PARITY(mbar, phase_parity) do { \
    uint32_t _mbar = (uint32_t)(mbar); \
    uint32_t _parity = (uint32_t)(phase_parity); \
    uint32_t _done_; \
    asm volatile( \
        "{\n\t.reg .pred p;\n\t" \
        "mbarrier.try_wait.parity.acquire.cta.shared::cta.b64 p, [%1], %2;\n\t" \
        "selp.b32 %0, 1, 0, p;\n\t}" \
        : "=r"(_done_) : "r"(_mbar), "r"(_parity) : "memory"); \
    if (!_done_) { \
        asm volatile( \
            "{\n\t.reg .pred P1;\n\t" \
            "WAIT_LOOP_%=:\n\t" \
            "mbarrier.try_wait.parity.acquire.cta.shared::cta.b64 P1, [%0], %1, 0x989680;\n\t" \
            "@P1 bra.uni WAIT_DONE_%=;\n\t" \
            "bra.uni WAIT_LOOP_%=;\n\t" \
            "WAIT_DONE_%=:\n\t}" \
            :: "r"(_mbar), "r"(_parity) : "memory"); \
    } \
} while (0)

#define TMA_LOAD_3D(smem_addr, tensor_map, cx, cy, cz, mbar) \
    asm volatile( \
        "cp.async.bulk.tensor.3d.shared::cta.global.tile.mbarrier::complete_tx::bytes " \
        "[%0], [%1, {%2, %3, %4}], [%5];" \
        :: "r"((uint32_t)(smem_addr)), "l"(tensor_map), \
           "r"((int32_t)(cx)), "r"((int32_t)(cy)), "r"((int32_t)(cz)), \
           "r"((uint32_t)(mbar)) : "memory")

#define FENCE_PROXY_ASYNC_SHARED_CTA() \
    asm volatile("fence.proxy.async.shared::cta;" ::: "memory")

// ldmatrix x4 (non-transposed), SW128-swizzled shared addresses
__device__ __forceinline__ void ldsm_x4(uint32_t& r0, uint32_t& r1,
                                        uint32_t& r2, uint32_t& r3, uint32_t addr) {
    asm volatile("ldmatrix.sync.aligned.m8n8.x4.shared.b16 {%0,%1,%2,%3}, [%4];"
                 : "=r"(r0), "=r"(r1), "=r"(r2), "=r"(r3) : "r"(addr));
}

// fp16 HMMA, fp32 accumulate
__device__ __forceinline__ void mma16816(float* c, const uint32_t* a, const uint32_t* b) {
    asm volatile(
        "mma.sync.aligned.m16n8k16.row.col.f32.f16.f16.f32 "
        "{%0,%1,%2,%3}, {%4,%5,%6,%7}, {%8,%9}, {%0,%1,%2,%3};"
        : "+f"(c[0]), "+f"(c[1]), "+f"(c[2]), "+f"(c[3])
        : "r"(a[0]), "r"(a[1]), "r"(a[2]), "r"(a[3]), "r"(b[0]), "r"(b[1]));
}

// ---------------------------------------------------------------------------
// Conversion kernels: fp32 -> fp16 (x), fp32 -> sign() fp16 (weight)
// ---------------------------------------------------------------------------
__device__ __forceinline__ uint32_t pack2h(float a, float b) {
    __half2 h = __floats2half2_rn(a, b);
    return *reinterpret_cast<uint32_t*>(&h);
}
__device__ __forceinline__ float fsgn(float v) {
    return (v > 0.0f) ? 1.0f : ((v < 0.0f) ? -1.0f : 0.0f);
}

__global__ void cvt_x_kernel(const float4* __restrict__ in, uint4* __restrict__ outv, int n8) {
    int i = blockIdx.x * blockDim.x + threadIdx.x;
    if (i < n8) {
        float4 a = in[2 * i];
        float4 b = in[2 * i + 1];
        uint4 o;
        o.x = pack2h(a.x, a.y); o.y = pack2h(a.z, a.w);
        o.z = pack2h(b.x, b.y); o.w = pack2h(b.z, b.w);
        outv[i] = o;
    }
}

__global__ void cvt_w_kernel(const float4* __restrict__ in, uint4* __restrict__ outv, int n8) {
    int i = blockIdx.x * blockDim.x + threadIdx.x;
    if (i < n8) {
        float4 a = in[2 * i];
        float4 b = in[2 * i + 1];
        uint4 o;
        o.x = pack2h(fsgn(a.x), fsgn(a.y)); o.y = pack2h(fsgn(a.z), fsgn(a.w));
        o.z = pack2h(fsgn(b.x), fsgn(b.y)); o.w = pack2h(fsgn(b.z), fsgn(b.w));
        outv[i] = o;
    }
}

// ---------------------------------------------------------------------------
// GEMM: TMA pipeline (4 stages) + ldmatrix + mma.sync m16n8k16
//   8 compute warps: 2 (M) x 4 (N), warp tile 64x64, + 1 producer warp
// ---------------------------------------------------------------------------
__global__ void __launch_bounds__(NTHREADS, 1)
mmf_gemm_kernel(const __grid_constant__ CUtensorMap tmap_a,
                const __grid_constant__ CUtensorMap tmap_b,
                const float* __restrict__ bias,
                const float* __restrict__ scale,
                float* __restrict__ out) {
    extern __shared__ char smem_raw[];
    uint32_t sb0 = smem_to_u32(smem_raw);
    uint32_t sb  = (sb0 + 1023u) & ~1023u;   // 1024-aligned (SW128)

    const int tid  = threadIdx.x;
    const int wid  = tid >> 5;
    const int lane = tid & 31;

    // Supertiles of 8 m-tiles x 16 n-tiles for L2 locality
    const int cid   = blockIdx.x;
    const int grp   = cid >> 7;            // 128 CTAs per supertile group
    const int w     = cid & 127;
    const int m0    = ((grp << 3) + (w & 7)) * BM;
    const int n0    = (w >> 3) * BN;

    if (tid == 0) {
        #pragma unroll
        for (int s = 0; s < STAGES; s++) {
            MBARRIER_INIT(sb + OFF_FULL  + 8 * s, 1);   // tx-driven
            MBARRIER_INIT(sb + OFF_EMPTY + 8 * s, 8);   // 8 compute warps
        }
        FENCE_PROXY_ASYNC_SHARED_CTA();
    }
    __syncthreads();

    // ---------------- producer warp (wid == 8) ----------------
    if (wid == 8) {
        if (elect_one_pred()) {
            for (int c = 0; c < NCHUNK; c++) {
                const int s = c & (STAGES - 1);
                if (c >= STAGES)
                    MBARRIER_WAIT_PARITY(sb + OFF_EMPTY + 8 * s,
                                         (uint32_t)(((c - STAGES) >> 2) & 1));
                const uint32_t fb = sb + OFF_FULL + 8 * s;
                MBARRIER_EXPECT_TX(fb, STAGE_BYTES);
                const uint32_t abase = sb + OFF_DATA + s * STAGE_BYTES;
                TMA_LOAD_3D(abase,           &tmap_a, c * BK, m0, 0, fb);
                TMA_LOAD_3D(abase + A_BYTES, &tmap_b, c * BK, n0, 0, fb);
            }
        }
        return;
    }

    // ---------------- compute warps (wid 0..7) ----------------
    const int wm = wid & 1;        // 0..1  -> rows [wm*64, +64)
    const int wn = wid >> 1;       // 0..3  -> cols [wn*64, +64)

    // ldmatrix lane addressing (SW128-swizzled)
    // A: 16x16 tiles, lanes 0..15 rows klo, 16..31 rows khi
    const int rA    = lane & 15;                 // row within 16-tile
    const int kbA   = (lane >> 4) * 16;          // 16B column offset
    const int mskA  = (rA & 7) << 4;
    // B: two n8-tiles per x4: q=l>>3: {nlo/klo, nlo/khi, nhi/klo, nhi/khi}
    const int q     = lane >> 3;
    const int rB    = ((q >> 1) << 3) + (lane & 7);
    const int kbB   = (q & 1) * 16;
    const int mskB  = (lane & 7) << 4;

    float acc[4][8][4];
    #pragma unroll
    for (int i = 0; i < 4; i++)
        #pragma unroll
        for (int j = 0; j < 8; j++)
            #pragma unroll
            for (int t = 0; t < 4; t++) acc[i][j][t] = 0.0f;

    for (int c = 0; c < NCHUNK; c++) {
        const int s = c & (STAGES - 1);
        MBARRIER_WAIT_PARITY(sb + OFF_FULL + 8 * s, (uint32_t)((c >> 2) & 1));
        const uint32_t aT = sb + OFF_DATA + s * STAGE_BYTES;
        const uint32_t bT = aT + A_BYTES;

        #pragma unroll
        for (int ks = 0; ks < 4; ks++) {
            uint32_t af[4][4];
            uint32_t bf[4][4];
            const int kA = (ks * 32 + kbA) ^ mskA;
            const int kB = (ks * 32 + kbB) ^ mskB;
            #pragma unroll
            for (int i = 0; i < 4; i++) {
                const int row = wm * 64 + i * 16 + rA;
                ldsm_x4(af[i][0], af[i][1], af[i][2], af[i][3],
                        aT + row * 128 + kA);
            }
            #pragma unroll
            for (int j2 = 0; j2 < 4; j2++) {
                const int row = wn * 64 + j2 * 16 + rB;
                ldsm_x4(bf[j2][0], bf[j2][1], bf[j2][2], bf[j2][3],
                        bT + row * 128 + kB);
            }
            #pragma unroll
            for (int i = 0; i < 4; i++) {
                #pragma unroll
                for (int j2 = 0; j2 < 4; j2++) {
                    mma16816(acc[i][2 * j2 + 0], af[i], &bf[j2][0]);
                    mma16816(acc[i][2 * j2 + 1], af[i], &bf[j2][2]);
                }
            }
        }
        // all this warp's reads of stage s are complete (mma issued in-order)
        if ((lane & 31) == 0) MBARRIER_ARRIVE(sb + OFF_EMPTY + 8 * s);
    }

    // ---------------- epilogue: out = scale * (acc + bias) ----------------
    const float scl = __ldg(scale);
    const int gid = lane >> 2;     // 0..7
    const int tig = lane & 3;      // 0..3

    float2 bb[8];
    #pragma unroll
    for (int j = 0; j < 8; j++) {
        const int col = n0 + wn * 64 + j * 8 + tig * 2;
        bb[j] = *reinterpret_cast<const float2*>(bias + col);
    }

    #pragma unroll
    for (int i = 0; i < 4; i++) {
        const int row0 = m0 + wm * 64 + i * 16 + gid;
        float* p0 = out + (size_t)row0 * DOUT;
        float* p1 = p0 + (size_t)8 * DOUT;
        #pragma unroll
        for (int j = 0; j < 8; j++) {
            const int col = n0 + wn * 64 + j * 8 + tig * 2;
            float2 v0, v1;
            v0.x = scl * (acc[i][j][0] + bb[j].x);
            v0.y = scl * (acc[i][j][1] + bb[j].y);
            v1.x = scl * (acc[i][j][2] + bb[j].x);
            v1.y = scl * (acc[i][j][3] + bb[j].y);
            *reinterpret_cast<float2*>(p0 + col) = v0;
            *reinterpret_cast<float2*>(p1 + col) = v1;
        }
    }
}

// ---------------------------------------------------------------------------
// Host launch
// ---------------------------------------------------------------------------
typedef CUresult (*PFN_encodeTiled_t)(
    CUtensorMap*, CUtensorMapDataType, cuuint32_t, void*,
    const cuuint64_t*, const cuuint64_t*, const cuuint32_t*, const cuuint32_t*,
    CUtensorMapInterleave, CUtensorMapSwizzle, CUtensorMapL2promotion,
    CUtensorMapFloatOOBfill);

extern "C" void kernel_launch(void* const* d_in, const int* in_sizes, int n_in,
                              void* d_out, int out_size) {
    (void)in_sizes; (void)n_in; (void)out_size;
    const float* x     = (const float*)d_in[0];
    const float* wgt   = (const float*)d_in[1];
    const float* bias  = (const float*)d_in[2];
    const float* scale = (const float*)d_in[3];
    float* out = (float*)d_out;

    void *xh = nullptr, *wh = nullptr;
    cudaGetSymbolAddress(&xh, g_xh);
    cudaGetSymbolAddress(&wh, g_wh);

    // 1) fp32 -> fp16 conversions into scratch
    {
        const int n8x = (NROWS * DIN) / 8;
        const int n8w = (DOUT * DIN) / 8;
        cvt_x_kernel<<<(n8x + 255) / 256, 256>>>((const float4*)x, (uint4*)xh, n8x);
        cvt_w_kernel<<<(n8w + 255) / 256, 256>>>((const float4*)wgt, (uint4*)wh, n8w);
    }

    // 2) TMA descriptors
    PFN_encodeTiled_t encode = nullptr;
    {
        void* pfn = nullptr;
        cudaDriverEntryPointQueryResult qr;
#if CUDART_VERSION >= 12050
        cudaGetDriverEntryPointByVersion("cuTensorMapEncodeTiled", &pfn, 12000,
                                         cudaEnableDefault, &qr);
#else
        cudaGetDriverEntryPoint("cuTensorMapEncodeTiled", &pfn,
                                cudaEnableDefault, &qr);
#endif
        encode = (PFN_encodeTiled_t)pfn;
    }

    CUtensorMap ta{}, tb{};
    {
        cuuint64_t dimsA[3] = {DIN, NROWS, 1};
        cuuint64_t strA[2]  = {(cuuint64_t)DIN * 2, (cuuint64_t)NROWS * DIN * 2};
        cuuint32_t boxA[3]  = {BK, BM, 1};      // 64 fp16 = 128B rows (SW128)
        cuuint32_t es[3]    = {1, 1, 1};
        encode(&ta, CU_TENSOR_MAP_DATA_TYPE_FLOAT16, 3, xh, dimsA, strA, boxA, es,
               CU_TENSOR_MAP_INTERLEAVE_NONE, CU_TENSOR_MAP_SWIZZLE_128B,
               CU_TENSOR_MAP_L2_PROMOTION_L2_128B, CU_TENSOR_MAP_FLOAT_OOB_FILL_NONE);

        cuuint64_t dimsB[3] = {DIN, DOUT, 1};
        cuuint64_t strB[2]  = {(cuuint64_t)DIN * 2, (cuuint64_t)DOUT * DIN * 2};
        cuuint32_t boxB[3]  = {BK, BN, 1};      // 256-row B tile
        encode(&tb, CU_TENSOR_MAP_DATA_TYPE_FLOAT16, 3, wh, dimsB, strB, boxB, es,
               CU_TENSOR_MAP_INTERLEAVE_NONE, CU_TENSOR_MAP_SWIZZLE_128B,
               CU_TENSOR_MAP_L2_PROMOTION_L2_128B, CU_TENSOR_MAP_FLOAT_OOB_FILL_NONE);
    }

    // 3) GEMM: 1024 CTAs x 288 threads, ~194KB dyn SMEM, 1 CTA/SM
    cudaFuncSetAttribute(mmf_gemm_kernel,
                         cudaFuncAttributeMaxDynamicSharedMemorySize, SMEM_NEED);
    mmf_gemm_kernel<<<(NROWS / BM) * (DOUT / BN), NTHREADS, SMEM_NEED>>>(
        ta, tb, bias, scale, out);
}

// round 15
// speedup vs baseline: 1.0339x; 1.0320x over previous
#include <cuda_runtime.h>
#include <cuda.h>
#include <cuda_fp16.h>
#include <cstdint>

// ---------------------------------------------------------------------------
// Problem dims
// ---------------------------------------------------------------------------
#define NROWS 8192
#define DIN   4096
#define DOUT  4096

// GEMM tiling
#define BM 128
#define BN 256
#define BK 64                       // 64 fp16 = 128B rows (SW128)
#define STAGES 4
#define NCHUNK (DIN / BK)           // 64

#define A_BYTES (BM * BK * 2)       // 16384
#define B_BYTES (BN * BK * 2)       // 32768
#define STAGE_BYTES (A_BYTES + B_BYTES)   // 49152

// SMEM offsets (from 1024-aligned base): [0..31] full mbars, [32..63] empty mbars
#define OFF_FULL  0
#define OFF_EMPTY 32
#define OFF_DATA  1024
#define SMEM_NEED (OFF_DATA + STAGES * STAGE_BYTES + 1024)   // align slack

#define NCWARPS  16                 // compute warps: 4 (M, 32 rows) x 4 (N, 64 cols)
#define NTHREADS 544                // 16 compute warps + 1 producer warp

// fp16 scratch (allocation-free: __device__ globals)
__device__ __align__(1024) __half g_xh[(size_t)NROWS * DIN];   // 64 MiB
__device__ __align__(1024) __half g_wh[(size_t)DOUT * DIN];    // 32 MiB

// ---------------------------------------------------------------------------
// PTX helpers (baseline sm_90 features only — NO 'a'-suffix instructions)
// ---------------------------------------------------------------------------
__device__ __forceinline__ uint32_t elect_one_pred() {
    uint32_t pred;
    asm volatile(
        "{\n\t.reg .pred p;\n\telect.sync _|p, 0xFFFFFFFF;\n\t"
        "selp.b32 %0, 1, 0, p;\n\t}" : "=r"(pred));
    return pred;
}

__device__ __forceinline__ uint32_t smem_to_u32(const void* p) {
    uint32_t a;
    asm("{ .reg .u64 t; cvta.to.shared.u64 t, %1; cvt.u32.u64 %0, t; }"
        : "=r"(a) : "l"(p));
    return a;
}

#define MBARRIER_INIT(mbar, count) \
    asm volatile("mbarrier.init.shared.b64 [%0], %1;" \
        :: "r"((uint32_t)(mbar)), "r"((uint32_t)(count)) : "memory")

#define MBARRIER_EXPECT_TX(mbar, tx_bytes) \
    asm volatile("mbarrier.arrive.expect_tx.shared.b64 _, [%0], %1;" \
        :: "r"((uint32_t)(mbar)), "r"((uint32_t)(tx_bytes)) : "memory")

#define MBARRIER_ARRIVE(mbar) \
    asm volatile("mbarrier.arrive.shared.b64 _, [%0];" \
        :: "r"((uint32_t)(mbar)) : "memory")

#define MBARRIER_WAIT_PARITY(mbar, phase_parity) do { \
    uint32_t _mbar = (uint32_t)(mbar); \
    uint32_t _parity = (uint32_t)(phase_parity); \
    uint32_t _done_; \
    asm volatile( \
        "{\n\t.reg .pred p;\n\t" \
        "mbarrier.try_wait.parity.acquire.cta.shared::cta.b64 p, [%1], %2;\n\t" \
        "selp.b32 %0, 1, 0, p;\n\t}" \
        : "=r"(_done_) : "r"(_mbar), "r"(_parity) : "memory"); \
    if (!_done_) { \
        asm volatile( \
            "{\n\t.reg .pred P1;\n\t" \
            "WAIT_LOOP_%=:\n\t" \
            "mbarrier.try_wait.parity.acquire.cta.shared::cta.b64 P1, [%0], %1, 0x989680;\n\t" \
            "@P1 bra.uni WAIT_DONE_%=;\n\t" \
            "bra.uni WAIT_LOOP_%=;\n\t" \
            "WAIT_DONE_%=:\n\t}" \
            :: "r"(_mbar), "r"(_parity) : "memory"); \
    } \
} while (0)

#define TMA_LOAD_3D(smem_addr, tensor_map, cx, cy, cz, mbar) \
    asm volatile( \
        "cp.async.bulk.tensor.3d.shared::cta.global.tile.mbarrier::complete_tx::bytes " \
        "[%0], [%1, {%2, %3, %4}], [%5];" \
        :: "r"((uint32_t)(smem_addr)), "l"(tensor_map), \
           "r"((int32_t)(cx)), "r"((int32_t)(cy)), "r"((int32_t)(cz)), \
           "r"((uint32_t)(mbar)) : "memory")

#define FENCE_PROXY_ASYNC_SHARED_CTA() \
    asm volatile("fence.proxy.async.shared::cta;" ::: "memory")

// ldmatrix x4 (non-transposed), SW128-swizzled shared addresses
__device__ __forceinline__ void ldsm_x4(uint32_t& r0, uint32_t& r1,
                                        uint32_t& r2, uint32_t& r3, uint32_t addr) {
    asm volatile("ldmatrix.sync.aligned.m8n8.x4.shared.b16 {%0,%1,%2,%3}, [%4];"
                 : "=r"(r0), "=r"(r1), "=r"(r2), "=r"(r3) : "r"(addr));
}

// fp16 HMMA, fp32 accumulate
__device__ __forceinline__ void mma16816(float* c, const uint32_t* a, const uint32_t* b) {
    asm volatile(
        "mma.sync.aligned.m16n8k16.row.col.f32.f16.f16.f32 "
        "{%0,%1,%2,%3}, {%4,%5,%6,%7}, {%8,%9}, {%0,%1,%2,%3};"
        : "+f"(c[0]), "+f"(c[1]), "+f"(c[2]), "+f"(c[3])
        : "r"(a[0]), "r"(a[1]), "r"(a[2]), "r"(a[3]), "r"(b[0]), "r"(b[1]));
}

// ---------------------------------------------------------------------------
// Fused conversion kernel: fp32 -> fp16 (x), fp32 -> sign() fp16 (weight)
// ---------------------------------------------------------------------------
#define N8X ((NROWS * DIN) / 8)     // 4194304 x-vectors (8 floats each)
#define N8W ((DOUT * DIN) / 8)      // 2097152 w-vectors

__device__ __forceinline__ uint32_t pack2h(float a, float b) {
    __half2 h = __floats2half2_rn(a, b);
    return *reinterpret_cast<uint32_t*>(&h);
}
__device__ __forceinline__ float fsgn(float v) {
    return (v > 0.0f) ? 1.0f : ((v < 0.0f) ? -1.0f : 0.0f);
}

__global__ void cvt_fused_kernel(const float4* __restrict__ xin,
                                 const float4* __restrict__ win,
                                 uint4* __restrict__ xo,
                                 uint4* __restrict__ wo) {
    int i = blockIdx.x * blockDim.x + threadIdx.x;
    if (i < N8X) {
        float4 a = xin[2 * i];
        float4 b = xin[2 * i + 1];
        uint4 o;
        o.x = pack2h(a.x, a.y); o.y = pack2h(a.z, a.w);
        o.z = pack2h(b.x, b.y); o.w = pack2h(b.z, b.w);
        xo[i] = o;
    } else {
        int j = i - N8X;
        if (j < N8W) {
            float4 a = win[2 * j];
            float4 b = win[2 * j + 1];
            uint4 o;
            o.x = pack2h(fsgn(a.x), fsgn(a.y)); o.y = pack2h(fsgn(a.z), fsgn(a.w));
            o.z = pack2h(fsgn(b.x), fsgn(b.y)); o.w = pack2h(fsgn(b.z), fsgn(b.w));
            wo[j] = o;
        }
    }
}

// ---------------------------------------------------------------------------
// GEMM: TMA pipeline (4 stages) + ldmatrix + mma.sync m16n8k16
//   16 compute warps: 4 (M, 32 rows) x 4 (N, 64 cols), + 1 producer warp
//   (4 compute warps per SMSP to keep the tensor pipe fed through LDSM /
//    barrier bubbles)
// ---------------------------------------------------------------------------
__global__ void __launch_bounds__(NTHREADS, 1)
mmf_gemm_kernel(const __grid_constant__ CUtensorMap tmap_a,
                const __grid_constant__ CUtensorMap tmap_b,
                const float* __restrict__ bias,
                const float* __restrict__ scale,
                float* __restrict__ out) {
    extern __shared__ char smem_raw[];
    uint32_t sb0 = smem_to_u32(smem_raw);
    uint32_t sb  = (sb0 + 1023u) & ~1023u;   // 1024-aligned (SW128)

    const int tid  = threadIdx.x;
    const int wid  = tid >> 5;
    const int lane = tid & 31;

    // Supertiles of 8 m-tiles x 16 n-tiles for L2 locality
    const int cid   = blockIdx.x;
    const int grp   = cid >> 7;            // 128 CTAs per supertile group
    const int w     = cid & 127;
    const int m0    = ((grp << 3) + (w & 7)) * BM;
    const int n0    = (w >> 3) * BN;

    if (tid == 0) {
        #pragma unroll
        for (int s = 0; s < STAGES; s++) {
            MBARRIER_INIT(sb + OFF_FULL  + 8 * s, 1);        // tx-driven
            MBARRIER_INIT(sb + OFF_EMPTY + 8 * s, NCWARPS);  // 16 compute warps
        }
        FENCE_PROXY_ASYNC_SHARED_CTA();
    }
    __syncthreads();

    // ---------------- producer warp (wid == 16) ----------------
    if (wid == NCWARPS) {
        if (elect_one_pred()) {
            for (int c = 0; c < NCHUNK; c++) {
                const int s = c & (STAGES - 1);
                if (c >= STAGES)
                    MBARRIER_WAIT_PARITY(sb + OFF_EMPTY + 8 * s,
                                         (uint32_t)(((c - STAGES) >> 2) & 1));
                const uint32_t fb = sb + OFF_FULL + 8 * s;
                MBARRIER_EXPECT_TX(fb, STAGE_BYTES);
                const uint32_t abase = sb + OFF_DATA + s * STAGE_BYTES;
                TMA_LOAD_3D(abase,           &tmap_a, c * BK, m0, 0, fb);
                TMA_LOAD_3D(abase + A_BYTES, &tmap_b, c * BK, n0, 0, fb);
            }
        }
        return;
    }

    // ---------------- compute warps (wid 0..15) ----------------
    const int wm = wid & 3;        // 0..3  -> rows [wm*32, +32)
    const int wn = wid >> 2;       // 0..3  -> cols [wn*64, +64)

    // ldmatrix lane addressing (SW128-swizzled)
    // A: 16x16 tiles, lanes 0..15 rows klo, 16..31 rows khi
    const int rA    = lane & 15;                 // row within 16-tile
    const int kbA   = (lane >> 4) * 16;          // 16B column offset
    const int mskA  = (rA & 7) << 4;
    // B: two n8-tiles per x4: q=l>>3: {nlo/klo, nlo/khi, nhi/klo, nhi/khi}
    const int q     = lane >> 3;
    const int rB    = ((q >> 1) << 3) + (lane & 7);
    const int kbB   = (q & 1) * 16;
    const int mskB  = (lane & 7) << 4;

    float acc[2][8][4];
    #pragma unroll
    for (int i = 0; i < 2; i++)
        #pragma unroll
        for (int j = 0; j < 8; j++)
            #pragma unroll
            for (int t = 0; t < 4; t++) acc[i][j][t] = 0.0f;

    for (int c = 0; c < NCHUNK; c++) {
        const int s = c & (STAGES - 1);
        MBARRIER_WAIT_PARITY(sb + OFF_FULL + 8 * s, (uint32_t)((c >> 2) & 1));
        const uint32_t aT = sb + OFF_DATA + s * STAGE_BYTES;
        const uint32_t bT = aT + A_BYTES;

        #pragma unroll
        for (int ks = 0; ks < 4; ks++) {
            uint32_t af[2][4];
            uint32_t bf[4][4];
            const int kA = (ks * 32 + kbA) ^ mskA;
            const int kB = (ks * 32 + kbB) ^ mskB;
            #pragma unroll
            for (int i = 0; i < 2; i++) {
                const int row = wm * 32 + i * 16 + rA;
                ldsm_x4(af[i][0], af[i][1], af[i][2], af[i][3],
                        aT + row * 128 + kA);
            }
            #pragma unroll
            for (int j2 = 0; j2 < 4; j2++) {
                const int row = wn * 64 + j2 * 16 + rB;
                ldsm_x4(bf[j2][0], bf[j2][1], bf[j2][2], bf[j2][3],
                        bT + row * 128 + kB);
            }
            #pragma unroll
            for (int i = 0; i < 2; i++) {
                #pragma unroll
                for (int j2 = 0; j2 < 4; j2++) {
                    mma16816(acc[i][2 * j2 + 0], af[i], &bf[j2][0]);
                    mma16816(acc[i][2 * j2 + 1], af[i], &bf[j2][2]);
                }
            }
        }
        // all this warp's reads of stage s are complete (mma issued in-order)
        if ((lane & 31) == 0) MBARRIER_ARRIVE(sb + OFF_EMPTY + 8 * s);
    }

    // ---------------- epilogue: out = scale * (acc + bias) ----------------
    const float scl = __ldg(scale);
    const int gid = lane >> 2;     // 0..7
    const int tig = lane & 3;      // 0..3

    float2 bb[8];
    #pragma unroll
    for (int j = 0; j < 8; j++) {
        const int col = n0 + wn * 64 + j * 8 + tig * 2;
        bb[j] = *reinterpret_cast<const float2*>(bias + col);
    }

    #pragma unroll
    for (int i = 0; i < 2; i++) {
        const int row0 = m0 + wm * 32 + i * 16 + gid;
        float* p0 = out + (size_t)row0 * DOUT;
        float* p1 = p0 + (size_t)8 * DOUT;
        #pragma unroll
        for (int j = 0; j < 8; j++) {
            const int col = n0 + wn * 64 + j * 8 + tig * 2;
            float2 v0, v1;
            v0.x = scl * (acc[i][j][0] + bb[j].x);
            v0.y = scl * (acc[i][j][1] + bb[j].y);
            v1.x = scl * (acc[i][j][2] + bb[j].x);
            v1.y = scl * (acc[i][j][3] + bb[j].y);
            *reinterpret_cast<float2*>(p0 + col) = v0;
            *reinterpret_cast<float2*>(p1 + col) = v1;
        }
    }
}

// ---------------------------------------------------------------------------
// Host launch
// ---------------------------------------------------------------------------
typedef CUresult (*PFN_encodeTiled_t)(
    CUtensorMap*, CUtensorMapDataType, cuuint32_t, void*,
    const cuuint64_t*, const cuuint64_t*, const cuuint32_t*, const cuuint32_t*,
    CUtensorMapInterleave, CUtensorMapSwizzle, CUtensorMapL2promotion,
    CUtensorMapFloatOOBfill);

extern "C" void kernel_launch(void* const* d_in, const int* in_sizes, int n_in,
                              void* d_out, int out_size) {
    (void)in_sizes; (void)n_in; (void)out_size;
    const float* x     = (const float*)d_in[0];
    const float* wgt   = (const float*)d_in[1];
    const float* bias  = (const float*)d_in[2];
    const float* scale = (const float*)d_in[3];
    float* out = (float*)d_out;

    void *xh = nullptr, *wh = nullptr;
    cudaGetSymbolAddress(&xh, g_xh);
    cudaGetSymbolAddress(&wh, g_wh);

    // 1) fused fp32 -> fp16 conversions into scratch (one launch)
    {
        const int total = N8X + N8W;
        cvt_fused_kernel<<<(total + 255) / 256, 256>>>(
            (const float4*)x, (const float4*)wgt, (uint4*)xh, (uint4*)wh);
    }

    // 2) TMA descriptors
    PFN_encodeTiled_t encode = nullptr;
    {
        void* pfn = nullptr;
        cudaDriverEntryPointQueryResult qr;
#if CUDART_VERSION >= 12050
        cudaGetDriverEntryPointByVersion("cuTensorMapEncodeTiled", &pfn, 12000,
                                         cudaEnableDefault, &qr);
#else
        cudaGetDriverEntryPoint("cuTensorMapEncodeTiled", &pfn,
                                cudaEnableDefault, &qr);
#endif
        encode = (PFN_encodeTiled_t)pfn;
    }

    CUtensorMap ta{}, tb{};
    {
        cuuint64_t dimsA[3] = {DIN, NROWS, 1};
        cuuint64_t strA[2]  = {(cuuint64_t)DIN * 2, (cuuint64_t)NROWS * DIN * 2};
        cuuint32_t boxA[3]  = {BK, BM, 1};      // 64 fp16 = 128B rows (SW128)
        cuuint32_t es[3]    = {1, 1, 1};
        encode(&ta, CU_TENSOR_MAP_DATA_TYPE_FLOAT16, 3, xh, dimsA, strA, boxA, es,
               CU_TENSOR_MAP_INTERLEAVE_NONE, CU_TENSOR_MAP_SWIZZLE_128B,
               CU_TENSOR_MAP_L2_PROMOTION_L2_128B, CU_TENSOR_MAP_FLOAT_OOB_FILL_NONE);

        cuuint64_t dimsB[3] = {DIN, DOUT, 1};
        cuuint64_t strB[2]  = {(cuuint64_t)DIN * 2, (cuuint64_t)DOUT * DIN * 2};
        cuuint32_t boxB[3]  = {BK, BN, 1};      // 256-row B tile
        encode(&tb, CU_TENSOR_MAP_DATA_TYPE_FLOAT16, 3, wh, dimsB, strB, boxB, es,
               CU_TENSOR_MAP_INTERLEAVE_NONE, CU_TENSOR_MAP_SWIZZLE_128B,
               CU_TENSOR_MAP_L2_PROMOTION_L2_128B, CU_TENSOR_MAP_FLOAT_OOB_FILL_NONE);
    }

    // 3) GEMM: 1024 CTAs x 544 threads, ~194KB dyn SMEM, 1 CTA/SM
    cudaFuncSetAttribute(mmf_gemm_kernel,
                         cudaFuncAttributeMaxDynamicSharedMemorySize, SMEM_NEED);
    mmf_gemm_kernel<<<(NROWS / BM) * (DOUT / BN), NTHREADS, SMEM_NEED>>>(
        ta, tb, bias, scale, out);
}